// round 14
// baseline (speedup 1.0000x reference)
#include <cuda_runtime.h>
#include <cstdint>

// ---------------- config ----------------
#define GRIDX  444             // 3 x 148, guaranteed resident with (128,3)
#define WPB    4               // warps per block
#define NBUF   3               // ring: 2 pair-groups in flight
#define NPAIRS 32768           // B/2
#define PFW    1344            // floats per pair buffer (2 x 672)

// ---------------- device scratch ----------------
__device__ float    g_part[GRIDX * 8];   // [blk][0..3]=S, [4..7]=Q
__device__ float    g_scale[8];
__device__ unsigned g_cnt  = 0;
__device__ unsigned g_flag = 0;

__device__ __forceinline__ void cp16(float* dst_smem, const float4* src_gmem) {
    unsigned d = (unsigned)__cvta_generic_to_shared(dst_smem);
    asm volatile("cp.async.cg.shared.global [%0], [%1], 16;\n"
                 :: "r"(d), "l"(src_gmem));
}

struct cf { float re, im; };
__device__ __forceinline__ cf cmul(cf a, cf b) { return {a.re*b.re - a.im*b.im, a.re*b.im + a.im*b.re}; }
__device__ __forceinline__ cf cadd(cf a, cf b) { return {a.re + b.re, a.im + b.im}; }

// ---------------- the one kernel --------------------------------------------
__global__ __launch_bounds__(128, 3) void k_all(
    const float* __restrict__ x, const float* __restrict__ W,
    const float* __restrict__ b, const float* __restrict__ vp,
    const float* __restrict__ gamma, const float* __restrict__ beta,
    float* __restrict__ out, int B)
{
    extern __shared__ float smv[];         // [NBUF][WPB][PFW] = 64512 B
    __shared__ float2 sU[256];             // sU[j*16+p] = U[p][j]
    __shared__ float  sPart[WPB][8];
    __shared__ float  sScale[8];
    __shared__ unsigned sTicket;

    const int tid  = threadIdx.x;
    const int w    = tid >> 5;
    const int lane = tid & 31;
    const int h    = lane >> 4;            // sample within pair
    const int p    = lane & 15;            // basis index
    const int bid  = blockIdx.x;

    const unsigned epoch = *(volatile unsigned*)&g_flag;   // stable at entry

    // contiguous pair-range for this block, split contiguously among warps
    const int p0 = (int)(((long)bid * NPAIRS) / GRIDX);
    const int p1 = (int)(((long)(bid + 1) * NPAIRS) / GRIDX);
    const int nb = p1 - p0;
    const int w0 = p0 + (nb * w) / WPB;
    const int w1 = p0 + (nb * (w + 1)) / WPB;
    const int n  = w1 - w0;                // pairs for this warp (~18-19)

    const float4* xv = reinterpret_cast<const float4*>(x);

    // stage pair (w0+t): 336 f4, contiguous 5376 B
    auto issue = [&](int t, int buf) {
        const float4* src = xv + (long)(w0 + t) * 2 * 196;
        float* dst = smv + (buf * WPB + w) * PFW;
        #pragma unroll
        for (int k = 0; k < 10; k++) {
            int idx = k*32 + lane;
            int so = (idx >= 168);                 // sample-within-pair
            cp16(dst + idx*4 + so*(672 - 168*4) + 0,   // see note below
                 src + so*196 + (idx - so*168));
        }
        if (lane < 16) {
            int idx = 320 + lane;
            cp16(dst + (idx - 168)*4 + 672, src + 196 + (idx - 168));
        }
        asm volatile("cp.async.commit_group;\n");
    };
    // note: dst layout is [sample0: 672 floats][sample1: 672 floats];
    // for idx<168: dst word = idx*4; for idx>=168: dst word = 672 + (idx-168)*4
    // idx*4 + so*(672 - 168*4) = idx*4 + so*0 ... 672-672=0 -> simplifies: ok.

    // prologue: 2 groups in flight
    issue(0, 0);
    if (n > 1) issue(1, 1);

    // ---- warp 0 builds U while prologue loads fly ----
    if (tid < 16) {
        const int j = tid;
        cf st[16];
        #pragma unroll
        for (int i = 0; i < 16; i++) st[i] = { (i == j) ? 1.0f : 0.0f, 0.0f };
        for (int l = 0; l < 3; l++) {
            for (int ww = 0; ww < 4; ww++) {
                float tx = vp[(l*4 + ww)*3 + 0];
                float ty = vp[(l*4 + ww)*3 + 1];
                float tz = vp[(l*4 + ww)*3 + 2];
                float cx, sx, cy, sy, cz, sz;
                sincosf(tx*0.5f, &sx, &cx);
                sincosf(ty*0.5f, &sy, &cy);
                sincosf(tz*0.5f, &sz, &cz);
                cf M00{ cy*cx,  sy*sx }, M01{ -sy*cx, -cy*sx };
                cf M10{ sy*cx, -cy*sx }, M11{  cy*cx, -sy*sx };
                cf e0{ cz, -sz }, e1{ cz, sz };
                cf G00 = cmul(e0, M00), G01 = cmul(e0, M01);
                cf G10 = cmul(e1, M10), G11 = cmul(e1, M11);
                int mask = 8 >> ww;
                #pragma unroll
                for (int i = 0; i < 16; i++) {
                    if (i & mask) continue;
                    cf a0 = st[i], a1 = st[i | mask];
                    st[i]        = cadd(cmul(G00, a0), cmul(G01, a1));
                    st[i | mask] = cadd(cmul(G10, a0), cmul(G11, a1));
                }
            }
            for (int ww = 0; ww < 3; ww++) {   // CNOT chain
                int cm = 8 >> ww, tm = 4 >> ww;
                cf tmp[16];
                #pragma unroll
                for (int i = 0; i < 16; i++) tmp[i] = st[(i & cm) ? (i ^ tm) : i];
                #pragma unroll
                for (int i = 0; i < 16; i++) st[i] = tmp[i];
            }
        }
        #pragma unroll
        for (int i = 0; i < 16; i++)
            sU[j*16 + i] = make_float2(st[i].re, st[i].im);
    }
    __syncthreads();

    // ---- per-lane constants ----
    float Ur[16], Ui[16];
    #pragma unroll
    for (int j = 0; j < 16; j++) {
        float2 u = sU[j*16 + p];
        Ur[j] = u.x; Ui[j] = u.y;
    }
    const float4 wrow = reinterpret_cast<const float4*>(W)[p];
    const float4 bv   = *reinterpret_cast<const float4*>(b);

    // conflict-free pooling column order: h=1 starts at column 3
    int colOff[6];
    #pragma unroll
    for (int i = 0; i < 6; i++) {
        int c = i + 3*h; if (c >= 6) c -= 6;
        colOff[i] = c;
    }

    float runS0=0, runS1=0, runS2=0, runS3=0;
    float runQ0=0, runQ1=0, runQ2=0, runQ3=0;

    const int cb = p & 3, rb = p >> 2;
    const int poolOff = h*672 + rb*168 + cb*6;

    int bsel = 0;                      // buffer of pair t
    int bIss = 2;                      // buffer of pair t+2
    for (int t = 0; t < n; t++) {
        if (t + 2 < n) {
            issue(t + 2, bIss);
            asm volatile("cp.async.wait_group 2;\n");
        } else if (t + 1 < n) {
            asm volatile("cp.async.wait_group 1;\n");
        } else {
            asm volatile("cp.async.wait_group 0;\n");
        }
        __syncwarp();

        // ---- pooling for bin p of sample h ----
        const float* s0f = smv + (bsel * WPB + w) * PFW + poolOff;
        float v = 0.f;
        #pragma unroll
        for (int i = 0; i < 6; i++) {
            const float* cp_ = s0f + colOff[i];
            #pragma unroll
            for (int dr = 0; dr < 6; dr++)
                v += cp_[dr*28];
        }
        v *= (1.0f / 36.0f);

        // ---- feats = pooled @ W + b (butterfly within 16-lane half) ----
        float f0 = v*wrow.x, f1 = v*wrow.y, f2 = v*wrow.z, f3 = v*wrow.w;
        #pragma unroll
        for (int m = 1; m < 16; m <<= 1) {
            f0 += __shfl_xor_sync(0xffffffffu, f0, m);
            f1 += __shfl_xor_sync(0xffffffffu, f1, m);
            f2 += __shfl_xor_sync(0xffffffffu, f2, m);
            f3 += __shfl_xor_sync(0xffffffffu, f3, m);
        }
        f0 += bv.x; f1 += bv.y; f2 += bv.z; f3 += bv.w;

        // ---- encoded product-state magnitudes ----
        float c0_,s_0,c1_,s_1,c2_,s_2,c3_,s_3;
        __sincosf(0.5f*f0, &s_0, &c0_);
        __sincosf(0.5f*f1, &s_1, &c1_);
        __sincosf(0.5f*f2, &s_2, &c2_);
        __sincosf(0.5f*f3, &s_3, &c3_);
        float w01[4] = { c0_*c1_, c0_*s_1, s_0*c1_, s_0*s_1 };
        float w23[4] = { c2_*c3_, c2_*s_3, s_2*c3_, s_2*s_3 };

        // ---- amp_p = sum_j U[p][j] * m_j * (-i)^popc(j) ----
        float ar = 0.f, ai = 0.f;
        #pragma unroll
        for (int j = 0; j < 16; j++) {
            float m = w01[j >> 2] * w23[j & 3];
            const int pm = __popc(j) & 3;
            if      (pm == 0) { ar += Ur[j]*m; ai += Ui[j]*m; }
            else if (pm == 1) { ar += Ui[j]*m; ai -= Ur[j]*m; }
            else if (pm == 2) { ar -= Ur[j]*m; ai -= Ui[j]*m; }
            else              { ar -= Ui[j]*m; ai += Ur[j]*m; }
        }
        float prob = ar*ar + ai*ai;

        // ---- expZ: Walsh-Hadamard butterfly over 16-lane half ----
        float v4 = prob;
        #pragma unroll
        for (int m = 1; m < 16; m <<= 1) {
            float o = __shfl_xor_sync(0xffffffffu, v4, m);
            v4 = (p & m) ? (o - v4) : (v4 + o);
        }
        const int hb = h << 4;
        float z0 = __shfl_sync(0xffffffffu, v4, hb + 8);
        float z1 = __shfl_sync(0xffffffffu, v4, hb + 4);
        float z2 = __shfl_sync(0xffffffffu, v4, hb + 2);
        float z3 = __shfl_sync(0xffffffffu, v4, hb + 1);

        if (p == 0) {
            long s = (long)(w0 + t) * 2 + h;
            reinterpret_cast<float4*>(out)[s] = make_float4(z0, z1, z2, z3);
            runS0 += z0; runS1 += z1; runS2 += z2; runS3 += z3;
            runQ0 += z0*z0; runQ1 += z1*z1; runQ2 += z2*z2; runQ3 += z3*z3;
        }
        __syncwarp();          // all lanes done before buffer reuse

        if (++bsel == NBUF) bsel = 0;
        if (++bIss == NBUF) bIss = 0;
    }

    // combine halves (lanes 0 and 16 hold stats)
    runS0 += __shfl_xor_sync(0xffffffffu, runS0, 16);
    runS1 += __shfl_xor_sync(0xffffffffu, runS1, 16);
    runS2 += __shfl_xor_sync(0xffffffffu, runS2, 16);
    runS3 += __shfl_xor_sync(0xffffffffu, runS3, 16);
    runQ0 += __shfl_xor_sync(0xffffffffu, runQ0, 16);
    runQ1 += __shfl_xor_sync(0xffffffffu, runQ1, 16);
    runQ2 += __shfl_xor_sync(0xffffffffu, runQ2, 16);
    runQ3 += __shfl_xor_sync(0xffffffffu, runQ3, 16);

    if (lane == 0) {
        sPart[w][0] = runS0; sPart[w][1] = runS1;
        sPart[w][2] = runS2; sPart[w][3] = runS3;
        sPart[w][4] = runQ0; sPart[w][5] = runQ1;
        sPart[w][6] = runQ2; sPart[w][7] = runQ3;
    }
    __syncthreads();

    if (tid < 8) {
        float t = sPart[0][tid] + sPart[1][tid] + sPart[2][tid] + sPart[3][tid];
        g_part[bid * 8 + tid] = t;
    }
    __threadfence();
    if (tid == 0) sTicket = atomicAdd(&g_cnt, 1u);
    __syncthreads();

    if ((sTicket % GRIDX) == GRIDX - 1) {
        __threadfence();
        float* sRed = reinterpret_cast<float*>(sU);   // 512-float scratch
        {
            int ch = tid & 7, row = tid >> 3;          // 16 rows x 8 channels
            float s = 0.f;
            for (int q = row; q < GRIDX; q += 16) s += __ldcg(&g_part[q*8 + ch]);
            sRed[row*8 + ch] = s;
        }
        __syncthreads();
        if (tid < 8) {
            float tt = 0.f;
            #pragma unroll
            for (int r = 0; r < 16; r++) tt += sRed[r*8 + tid];
            sRed[128 + tid] = tt;
        }
        __syncthreads();
        if (tid < 4) {
            float invB = 1.0f / (float)B;
            float mu  = sRed[128 + tid] * invB;
            float var = sRed[132 + tid] * invB - mu*mu;    // biased var
            float scw = gamma[tid] * rsqrtf(var + 1e-5f);
            g_scale[tid]     = scw;
            g_scale[4 + tid] = beta[tid] - mu * scw;
        }
        __threadfence();
        __syncthreads();
        if (tid == 0) atomicAdd(&g_flag, 1u);   // bump epoch
    }

    // ---- all blocks: wait for epoch bump ----
    if (tid == 0) {
        while (*(volatile unsigned*)&g_flag == epoch) __nanosleep(64);
    }
    __syncthreads();
    __threadfence();

    if (tid < 8) sScale[tid] = *(volatile float*)&g_scale[tid];
    __syncthreads();

    // ---- normalize own sample range [2*p0, 2*p1) ----
    {
        float4 scv = *reinterpret_cast<const float4*>(&sScale[0]);
        float4 shv = *reinterpret_cast<const float4*>(&sScale[4]);
        for (int i = 2*p0 + tid; i < 2*p1; i += 128) {
            float4 r = reinterpret_cast<float4*>(out)[i];
            r.x = r.x*scv.x + shv.x;
            r.y = r.y*scv.y + shv.y;
            r.z = r.z*scv.z + shv.z;
            r.w = r.w*scv.w + shv.w;
            reinterpret_cast<float4*>(out)[i] = r;
        }
    }
}

// ---------------- launch ----------------------------------------------------
extern "C" void kernel_launch(void* const* d_in, const int* in_sizes, int n_in,
                              void* d_out, int out_size)
{
    const float* x     = (const float*)d_in[0];  // [B,1,28,28]
    const float* W     = (const float*)d_in[1];  // [16,4]
    const float* b     = (const float*)d_in[2];  // [4]
    const float* vp    = (const float*)d_in[3];  // [3,4,3]
    const float* gamma = (const float*)d_in[4];  // [4]
    const float* beta  = (const float*)d_in[5];  // [4]
    float* out = (float*)d_out;                  // [B,4]

    int B = in_sizes[0] / 784;                   // 65536

    const int dynBytes = NBUF * WPB * PFW * 4;   // 64512
    cudaFuncSetAttribute(k_all, cudaFuncAttributeMaxDynamicSharedMemorySize, dynBytes);
    k_all<<<GRIDX, 128, dynBytes>>>(x, W, b, vp, gamma, beta, out, B);
}

// round 15
// speedup vs baseline: 1.1067x; 1.1067x over previous
#include <cuda_runtime.h>
#include <cstdint>

// ---------------- config ----------------
#define GRIDX  592             // 4 x 148, exactly resident with (128,4)
#define WPB    4               // warps per block
#define NPAIRS 32768           // B/2
#define PFW    1344            // floats per pair buffer (2 x 672)

// ---------------- device scratch ----------------
__device__ float    g_part[GRIDX * 8];   // [blk][0..3]=S, [4..7]=Q
__device__ float    g_scale[8];
__device__ unsigned g_cnt  = 0;
__device__ unsigned g_flag = 0;

__device__ __forceinline__ void cp16(float* dst_smem, const float4* src_gmem) {
    unsigned d = (unsigned)__cvta_generic_to_shared(dst_smem);
    asm volatile("cp.async.cg.shared.global [%0], [%1], 16;\n"
                 :: "r"(d), "l"(src_gmem));
}

struct cf { float re, im; };
__device__ __forceinline__ cf cmul(cf a, cf b) { return {a.re*b.re - a.im*b.im, a.re*b.im + a.im*b.re}; }
__device__ __forceinline__ cf cadd(cf a, cf b) { return {a.re + b.re, a.im + b.im}; }

// ---------------- the one kernel --------------------------------------------
__global__ __launch_bounds__(128, 4) void k_all(
    const float* __restrict__ x, const float* __restrict__ W,
    const float* __restrict__ b, const float* __restrict__ vp,
    const float* __restrict__ gamma, const float* __restrict__ beta,
    float* __restrict__ out, int B)
{
    __shared__ __align__(16) float smv[2][WPB][PFW];   // 43008 B pair buffers
    __shared__ float2 sU[256];             // sU[j*16+p] = U[p][j]
    __shared__ float  sPart[WPB][8];
    __shared__ float  sScale[8];
    __shared__ unsigned sTicket;

    const int tid  = threadIdx.x;
    const int w    = tid >> 5;
    const int lane = tid & 31;
    const int h    = lane >> 4;            // sample within pair
    const int p    = lane & 15;            // basis index
    const int bid  = blockIdx.x;

    const unsigned epoch = *(volatile unsigned*)&g_flag;   // stable at entry

    // contiguous pair-range for this block, split contiguously among warps
    const int p0 = (int)(((long)bid * NPAIRS) / GRIDX);
    const int p1 = (int)(((long)(bid + 1) * NPAIRS) / GRIDX);
    const int nb = p1 - p0;
    const int w0 = p0 + (nb * w) / WPB;
    const int w1 = p0 + (nb * (w + 1)) / WPB;
    const int n  = w1 - w0;                // pairs for this warp (~13-14)

    const float4* xv = reinterpret_cast<const float4*>(x);

    // stage pair (w0+t): 336 f4 = contiguous 5376 B, depth-1 double buffer
    auto issue = [&](int t, int buf) {
        const float4* src = xv + (long)(w0 + t) * 392;
        float* dst = &smv[buf][w][0];
        #pragma unroll
        for (int k = 0; k < 10; k++) {
            int idx = k*32 + lane;
            int so = (idx >= 168);
            cp16(dst + (idx - so*168)*4 + so*672, src + so*196 + (idx - so*168));
        }
        if (lane < 16) {
            int idx = 320 + lane;
            cp16(dst + (idx - 168)*4 + 672, src + 196 + (idx - 168));
        }
        asm volatile("cp.async.commit_group;\n");
    };

    if (n > 0) issue(0, 0);

    // ---- warp 0 builds U while prologue loads fly ----
    if (tid < 16) {
        const int j = tid;
        cf st[16];
        #pragma unroll
        for (int i = 0; i < 16; i++) st[i] = { (i == j) ? 1.0f : 0.0f, 0.0f };
        for (int l = 0; l < 3; l++) {
            for (int ww = 0; ww < 4; ww++) {
                float tx = vp[(l*4 + ww)*3 + 0];
                float ty = vp[(l*4 + ww)*3 + 1];
                float tz = vp[(l*4 + ww)*3 + 2];
                float cx, sx, cy, sy, cz, sz;
                sincosf(tx*0.5f, &sx, &cx);
                sincosf(ty*0.5f, &sy, &cy);
                sincosf(tz*0.5f, &sz, &cz);
                cf M00{ cy*cx,  sy*sx }, M01{ -sy*cx, -cy*sx };
                cf M10{ sy*cx, -cy*sx }, M11{  cy*cx, -sy*sx };
                cf e0{ cz, -sz }, e1{ cz, sz };
                cf G00 = cmul(e0, M00), G01 = cmul(e0, M01);
                cf G10 = cmul(e1, M10), G11 = cmul(e1, M11);
                int mask = 8 >> ww;
                #pragma unroll
                for (int i = 0; i < 16; i++) {
                    if (i & mask) continue;
                    cf a0 = st[i], a1 = st[i | mask];
                    st[i]        = cadd(cmul(G00, a0), cmul(G01, a1));
                    st[i | mask] = cadd(cmul(G10, a0), cmul(G11, a1));
                }
            }
            for (int ww = 0; ww < 3; ww++) {   // CNOT chain
                int cm = 8 >> ww, tm = 4 >> ww;
                cf tmp[16];
                #pragma unroll
                for (int i = 0; i < 16; i++) tmp[i] = st[(i & cm) ? (i ^ tm) : i];
                #pragma unroll
                for (int i = 0; i < 16; i++) st[i] = tmp[i];
            }
        }
        #pragma unroll
        for (int i = 0; i < 16; i++)
            sU[j*16 + i] = make_float2(st[i].re, st[i].im);
    }
    __syncthreads();

    // ---- per-lane constants ----
    float Ur[16], Ui[16];
    #pragma unroll
    for (int j = 0; j < 16; j++) {
        float2 u = sU[j*16 + p];
        Ur[j] = u.x; Ui[j] = u.y;
    }
    const float4 wrow = reinterpret_cast<const float4*>(W)[p];
    const float4 bv   = *reinterpret_cast<const float4*>(b);

    // conflict-free pooling column order: h=1 starts at column 3
    int colOff[6];
    #pragma unroll
    for (int i = 0; i < 6; i++) {
        int c = i + 3*h; if (c >= 6) c -= 6;
        colOff[i] = c;
    }

    float runS0=0, runS1=0, runS2=0, runS3=0;
    float runQ0=0, runQ1=0, runQ2=0, runQ3=0;

    const int cb = p & 3, rb = p >> 2;
    const int poolOff = h*672 + rb*168 + cb*6;

    for (int t = 0; t < n; t++) {
        if (t + 1 < n) {
            issue(t + 1, (t + 1) & 1);
            asm volatile("cp.async.wait_group 1;\n");
        } else {
            asm volatile("cp.async.wait_group 0;\n");
        }
        __syncwarp();

        // ---- pooling for bin p of sample h ----
        const float* s0f = &smv[t & 1][w][0] + poolOff;
        float v = 0.f;
        #pragma unroll
        for (int i = 0; i < 6; i++) {
            const float* cp_ = s0f + colOff[i];
            #pragma unroll
            for (int dr = 0; dr < 6; dr++)
                v += cp_[dr*28];
        }
        v *= (1.0f / 36.0f);

        // ---- feats = pooled @ W + b (butterfly within 16-lane half) ----
        float f0 = v*wrow.x, f1 = v*wrow.y, f2 = v*wrow.z, f3 = v*wrow.w;
        #pragma unroll
        for (int m = 1; m < 16; m <<= 1) {
            f0 += __shfl_xor_sync(0xffffffffu, f0, m);
            f1 += __shfl_xor_sync(0xffffffffu, f1, m);
            f2 += __shfl_xor_sync(0xffffffffu, f2, m);
            f3 += __shfl_xor_sync(0xffffffffu, f3, m);
        }
        f0 += bv.x; f1 += bv.y; f2 += bv.z; f3 += bv.w;

        // ---- encoded product-state magnitudes ----
        float c0_,s_0,c1_,s_1,c2_,s_2,c3_,s_3;
        __sincosf(0.5f*f0, &s_0, &c0_);
        __sincosf(0.5f*f1, &s_1, &c1_);
        __sincosf(0.5f*f2, &s_2, &c2_);
        __sincosf(0.5f*f3, &s_3, &c3_);
        float w01[4] = { c0_*c1_, c0_*s_1, s_0*c1_, s_0*s_1 };
        float w23[4] = { c2_*c3_, c2_*s_3, s_2*c3_, s_2*s_3 };

        // ---- amp_p = sum_j U[p][j] * m_j * (-i)^popc(j) ----
        float ar = 0.f, ai = 0.f;
        #pragma unroll
        for (int j = 0; j < 16; j++) {
            float m = w01[j >> 2] * w23[j & 3];
            const int pm = __popc(j) & 3;
            if      (pm == 0) { ar += Ur[j]*m; ai += Ui[j]*m; }
            else if (pm == 1) { ar += Ui[j]*m; ai -= Ur[j]*m; }
            else if (pm == 2) { ar -= Ur[j]*m; ai -= Ui[j]*m; }
            else              { ar -= Ui[j]*m; ai += Ur[j]*m; }
        }
        float prob = ar*ar + ai*ai;

        // ---- expZ: Walsh-Hadamard butterfly over 16-lane half ----
        float v4 = prob;
        #pragma unroll
        for (int m = 1; m < 16; m <<= 1) {
            float o = __shfl_xor_sync(0xffffffffu, v4, m);
            v4 = (p & m) ? (o - v4) : (v4 + o);
        }
        const int hb = h << 4;
        float z0 = __shfl_sync(0xffffffffu, v4, hb + 8);
        float z1 = __shfl_sync(0xffffffffu, v4, hb + 4);
        float z2 = __shfl_sync(0xffffffffu, v4, hb + 2);
        float z3 = __shfl_sync(0xffffffffu, v4, hb + 1);

        if (p == 0) {
            long s = (long)(w0 + t) * 2 + h;
            reinterpret_cast<float4*>(out)[s] = make_float4(z0, z1, z2, z3);
            runS0 += z0; runS1 += z1; runS2 += z2; runS3 += z3;
            runQ0 += z0*z0; runQ1 += z1*z1; runQ2 += z2*z2; runQ3 += z3*z3;
        }
        __syncwarp();     // all lanes done before buffer reuse
    }

    // combine halves (lanes 0 and 16 hold stats)
    runS0 += __shfl_xor_sync(0xffffffffu, runS0, 16);
    runS1 += __shfl_xor_sync(0xffffffffu, runS1, 16);
    runS2 += __shfl_xor_sync(0xffffffffu, runS2, 16);
    runS3 += __shfl_xor_sync(0xffffffffu, runS3, 16);
    runQ0 += __shfl_xor_sync(0xffffffffu, runQ0, 16);
    runQ1 += __shfl_xor_sync(0xffffffffu, runQ1, 16);
    runQ2 += __shfl_xor_sync(0xffffffffu, runQ2, 16);
    runQ3 += __shfl_xor_sync(0xffffffffu, runQ3, 16);

    if (lane == 0) {
        sPart[w][0] = runS0; sPart[w][1] = runS1;
        sPart[w][2] = runS2; sPart[w][3] = runS3;
        sPart[w][4] = runQ0; sPart[w][5] = runQ1;
        sPart[w][6] = runQ2; sPart[w][7] = runQ3;
    }
    __syncthreads();

    if (tid < 8) {
        float t = sPart[0][tid] + sPart[1][tid] + sPart[2][tid] + sPart[3][tid];
        g_part[bid * 8 + tid] = t;
    }
    __threadfence();
    if (tid == 0) sTicket = atomicAdd(&g_cnt, 1u);
    __syncthreads();

    if ((sTicket % GRIDX) == GRIDX - 1) {
        __threadfence();
        float* sRed = reinterpret_cast<float*>(sU);   // 512-float scratch
        {
            int ch = tid & 7, row = tid >> 3;          // 16 rows x 8 channels
            float s = 0.f;
            for (int q = row; q < GRIDX; q += 16) s += __ldcg(&g_part[q*8 + ch]);
            sRed[row*8 + ch] = s;
        }
        __syncthreads();
        if (tid < 8) {
            float tt = 0.f;
            #pragma unroll
            for (int r = 0; r < 16; r++) tt += sRed[r*8 + tid];
            sRed[128 + tid] = tt;
        }
        __syncthreads();
        if (tid < 4) {
            float invB = 1.0f / (float)B;
            float mu  = sRed[128 + tid] * invB;
            float var = sRed[132 + tid] * invB - mu*mu;    // biased var
            float scw = gamma[tid] * rsqrtf(var + 1e-5f);
            g_scale[tid]     = scw;
            g_scale[4 + tid] = beta[tid] - mu * scw;
        }
        __threadfence();
        __syncthreads();
        if (tid == 0) atomicAdd(&g_flag, 1u);   // bump epoch
    }

    // ---- all blocks: wait for epoch bump ----
    if (tid == 0) {
        while (*(volatile unsigned*)&g_flag == epoch) __nanosleep(64);
    }
    __syncthreads();
    __threadfence();

    if (tid < 8) sScale[tid] = *(volatile float*)&g_scale[tid];
    __syncthreads();

    // ---- normalize own sample range [2*p0, 2*p1) ----
    {
        float4 scv = *reinterpret_cast<const float4*>(&sScale[0]);
        float4 shv = *reinterpret_cast<const float4*>(&sScale[4]);
        for (int i = 2*p0 + tid; i < 2*p1; i += 128) {
            float4 r = reinterpret_cast<float4*>(out)[i];
            r.x = r.x*scv.x + shv.x;
            r.y = r.y*scv.y + shv.y;
            r.z = r.z*scv.z + shv.z;
            r.w = r.w*scv.w + shv.w;
            reinterpret_cast<float4*>(out)[i] = r;
        }
    }
}

// ---------------- launch ----------------------------------------------------
extern "C" void kernel_launch(void* const* d_in, const int* in_sizes, int n_in,
                              void* d_out, int out_size)
{
    const float* x     = (const float*)d_in[0];  // [B,1,28,28]
    const float* W     = (const float*)d_in[1];  // [16,4]
    const float* b     = (const float*)d_in[2];  // [4]
    const float* vp    = (const float*)d_in[3];  // [3,4,3]
    const float* gamma = (const float*)d_in[4];  // [4]
    const float* beta  = (const float*)d_in[5];  // [4]
    float* out = (float*)d_out;                  // [B,4]

    int B = in_sizes[0] / 784;                   // 65536

    k_all<<<GRIDX, 128>>>(x, W, b, vp, gamma, beta, out, B);
}

// round 16
// speedup vs baseline: 1.1513x; 1.0403x over previous
#include <cuda_runtime.h>
#include <cstdint>

// ---------------- config ----------------
#define GRIDX   592            // 4 x 148, exactly resident with (128,4)
#define WPB     4              // warps per block
#define NWARPS  (GRIDX * WPB)  // 2368
#define NPAIRS  32768          // B/2
#define CHP     4              // pairs per chunk
#define NCHUNKS (NPAIRS / CHP) // 8192
#define PFW     1344           // floats per pair buffer (2 x 672)

// ---------------- device scratch ----------------
__device__ float    g_part[GRIDX * 8];   // [blk][0..3]=S, [4..7]=Q
__device__ float    g_scale[8];
__device__ unsigned g_cnt  = 0;          // ticket counter (monotonic)
__device__ unsigned g_flag = 0;          // epoch (monotonic, +1 per launch)
__device__ unsigned g_work = 0;          // work counter (monotonic, +NCHUNKS per launch)

__device__ __forceinline__ void cp16(float* dst_smem, const float4* src_gmem) {
    unsigned d = (unsigned)__cvta_generic_to_shared(dst_smem);
    asm volatile("cp.async.cg.shared.global [%0], [%1], 16;\n"
                 :: "r"(d), "l"(src_gmem));
}

struct cf { float re, im; };
__device__ __forceinline__ cf cmul(cf a, cf b) { return {a.re*b.re - a.im*b.im, a.re*b.im + a.im*b.re}; }
__device__ __forceinline__ cf cadd(cf a, cf b) { return {a.re + b.re, a.im + b.im}; }

// ---------------- the one kernel --------------------------------------------
__global__ __launch_bounds__(128, 4) void k_all(
    const float* __restrict__ x, const float* __restrict__ W,
    const float* __restrict__ b, const float* __restrict__ vp,
    const float* __restrict__ gamma, const float* __restrict__ beta,
    float* __restrict__ out, int B)
{
    __shared__ __align__(16) float smv[2][WPB][PFW];   // 43008 B pair buffers
    __shared__ float2 sU[256];             // sU[j*16+p] = U[p][j]
    __shared__ float  sPart[WPB][8];
    __shared__ float  sScale[8];
    __shared__ unsigned sTicket;

    const int tid  = threadIdx.x;
    const int w    = tid >> 5;
    const int lane = tid & 31;
    const int h    = lane >> 4;            // sample within pair
    const int p    = lane & 15;            // basis index
    const int bid  = blockIdx.x;

    const unsigned epoch = *(volatile unsigned*)&g_flag;   // stable at entry
    const unsigned base  = epoch * (unsigned)NCHUNKS;      // work-counter base

    const float4* xv = reinterpret_cast<const float4*>(x);
    const int wgid = bid * WPB + w;        // global warp id = static first chunk

    // stage pair pr: 336 f4 = contiguous 5376 B, depth-1 double buffer
    auto issuePair = [&](int pr, int buf) {
        const float4* src = xv + (long)pr * 392;
        float* dst = &smv[buf][w][0];
        #pragma unroll
        for (int k = 0; k < 10; k++) {
            int idx = k*32 + lane;
            int so = (idx >= 168);
            cp16(dst + (idx - so*168)*4 + so*672, src + so*196 + (idx - so*168));
        }
        if (lane < 16) {
            int idx = 320 + lane;
            cp16(dst + (idx - 168)*4 + 672, src + 196 + (idx - 168));
        }
        asm volatile("cp.async.commit_group;\n");
    };

    // dynamic chunk grab (lane 0 atomics, warp-uniform result)
    auto grabNext = [&]() -> int {
        unsigned c = 0;
        if (lane == 0) c = atomicAdd(&g_work, 1u);
        c = __shfl_sync(0xffffffffu, c, 0);
        unsigned rel = c - base + (unsigned)NWARPS;
        return (rel < (unsigned)NCHUNKS) ? (int)rel : -1;
    };

    int curC = wgid;                       // static first chunk
    issuePair(curC * CHP, 0);

    // ---- warp 0 builds U while prologue loads fly ----
    if (tid < 16) {
        const int j = tid;
        cf st[16];
        #pragma unroll
        for (int i = 0; i < 16; i++) st[i] = { (i == j) ? 1.0f : 0.0f, 0.0f };
        for (int l = 0; l < 3; l++) {
            for (int ww = 0; ww < 4; ww++) {
                float tx = vp[(l*4 + ww)*3 + 0];
                float ty = vp[(l*4 + ww)*3 + 1];
                float tz = vp[(l*4 + ww)*3 + 2];
                float cx, sx, cy, sy, cz, sz;
                sincosf(tx*0.5f, &sx, &cx);
                sincosf(ty*0.5f, &sy, &cy);
                sincosf(tz*0.5f, &sz, &cz);
                cf M00{ cy*cx,  sy*sx }, M01{ -sy*cx, -cy*sx };
                cf M10{ sy*cx, -cy*sx }, M11{  cy*cx, -sy*sx };
                cf e0{ cz, -sz }, e1{ cz, sz };
                cf G00 = cmul(e0, M00), G01 = cmul(e0, M01);
                cf G10 = cmul(e1, M10), G11 = cmul(e1, M11);
                int mask = 8 >> ww;
                #pragma unroll
                for (int i = 0; i < 16; i++) {
                    if (i & mask) continue;
                    cf a0 = st[i], a1 = st[i | mask];
                    st[i]        = cadd(cmul(G00, a0), cmul(G01, a1));
                    st[i | mask] = cadd(cmul(G10, a0), cmul(G11, a1));
                }
            }
            for (int ww = 0; ww < 3; ww++) {   // CNOT chain
                int cm = 8 >> ww, tm = 4 >> ww;
                cf tmp[16];
                #pragma unroll
                for (int i = 0; i < 16; i++) tmp[i] = st[(i & cm) ? (i ^ tm) : i];
                #pragma unroll
                for (int i = 0; i < 16; i++) st[i] = tmp[i];
            }
        }
        #pragma unroll
        for (int i = 0; i < 16; i++)
            sU[j*16 + i] = make_float2(st[i].re, st[i].im);
    }
    __syncthreads();

    // ---- per-lane constants ----
    float Ur[16], Ui[16];
    #pragma unroll
    for (int j = 0; j < 16; j++) {
        float2 u = sU[j*16 + p];
        Ur[j] = u.x; Ui[j] = u.y;
    }
    const float4 wrow = reinterpret_cast<const float4*>(W)[p];
    const float4 bv   = *reinterpret_cast<const float4*>(b);

    // conflict-free pooling column order: h=1 starts at column 3
    int colOff[6];
    #pragma unroll
    for (int i = 0; i < 6; i++) {
        int c = i + 3*h; if (c >= 6) c -= 6;
        colOff[i] = c;
    }

    float runS0=0, runS1=0, runS2=0, runS3=0;
    float runQ0=0, runQ1=0, runQ2=0, runQ3=0;

    const int cb = p & 3, rb = p >> 2;
    const int poolOff = h*672 + rb*168 + cb*6;

    int buf = 0;
    while (curC >= 0) {
        int nextC = -1;
        #pragma unroll
        for (int t = 0; t < CHP; t++) {
            if (t + 1 < CHP) {
                issuePair(curC*CHP + t + 1, buf ^ 1);
                asm volatile("cp.async.wait_group 1;\n");
            } else {
                nextC = grabNext();
                if (nextC >= 0) {
                    issuePair(nextC*CHP, buf ^ 1);
                    asm volatile("cp.async.wait_group 1;\n");
                } else {
                    asm volatile("cp.async.wait_group 0;\n");
                }
            }
            __syncwarp();

            // ---- pooling for bin p of sample h ----
            const float* s0f = &smv[buf][w][0] + poolOff;
            float v = 0.f;
            #pragma unroll
            for (int i = 0; i < 6; i++) {
                const float* cp_ = s0f + colOff[i];
                #pragma unroll
                for (int dr = 0; dr < 6; dr++)
                    v += cp_[dr*28];
            }
            v *= (1.0f / 36.0f);

            // ---- feats = pooled @ W + b (butterfly within 16-lane half) ----
            float f0 = v*wrow.x, f1 = v*wrow.y, f2 = v*wrow.z, f3 = v*wrow.w;
            #pragma unroll
            for (int m = 1; m < 16; m <<= 1) {
                f0 += __shfl_xor_sync(0xffffffffu, f0, m);
                f1 += __shfl_xor_sync(0xffffffffu, f1, m);
                f2 += __shfl_xor_sync(0xffffffffu, f2, m);
                f3 += __shfl_xor_sync(0xffffffffu, f3, m);
            }
            f0 += bv.x; f1 += bv.y; f2 += bv.z; f3 += bv.w;

            // ---- encoded product-state magnitudes ----
            float c0_,s_0,c1_,s_1,c2_,s_2,c3_,s_3;
            __sincosf(0.5f*f0, &s_0, &c0_);
            __sincosf(0.5f*f1, &s_1, &c1_);
            __sincosf(0.5f*f2, &s_2, &c2_);
            __sincosf(0.5f*f3, &s_3, &c3_);
            float w01[4] = { c0_*c1_, c0_*s_1, s_0*c1_, s_0*s_1 };
            float w23[4] = { c2_*c3_, c2_*s_3, s_2*c3_, s_2*s_3 };

            // ---- amp_p = sum_j U[p][j] * m_j * (-i)^popc(j) ----
            float ar = 0.f, ai = 0.f;
            #pragma unroll
            for (int j = 0; j < 16; j++) {
                float m = w01[j >> 2] * w23[j & 3];
                const int pm = __popc(j) & 3;
                if      (pm == 0) { ar += Ur[j]*m; ai += Ui[j]*m; }
                else if (pm == 1) { ar += Ui[j]*m; ai -= Ur[j]*m; }
                else if (pm == 2) { ar -= Ur[j]*m; ai -= Ui[j]*m; }
                else              { ar -= Ui[j]*m; ai += Ur[j]*m; }
            }
            float prob = ar*ar + ai*ai;

            // ---- expZ: Walsh-Hadamard butterfly over 16-lane half ----
            float v4 = prob;
            #pragma unroll
            for (int m = 1; m < 16; m <<= 1) {
                float o = __shfl_xor_sync(0xffffffffu, v4, m);
                v4 = (p & m) ? (o - v4) : (v4 + o);
            }
            const int hb = h << 4;
            float z0 = __shfl_sync(0xffffffffu, v4, hb + 8);
            float z1 = __shfl_sync(0xffffffffu, v4, hb + 4);
            float z2 = __shfl_sync(0xffffffffu, v4, hb + 2);
            float z3 = __shfl_sync(0xffffffffu, v4, hb + 1);

            if (p == 0) {
                long s = (long)(curC*CHP + t) * 2 + h;
                reinterpret_cast<float4*>(out)[s] = make_float4(z0, z1, z2, z3);
                runS0 += z0; runS1 += z1; runS2 += z2; runS3 += z3;
                runQ0 += z0*z0; runQ1 += z1*z1; runQ2 += z2*z2; runQ3 += z3*z3;
            }
            __syncwarp();     // all lanes done before buffer reuse
            buf ^= 1;
        }
        curC = nextC;
    }

    // combine halves (lanes 0 and 16 hold stats)
    runS0 += __shfl_xor_sync(0xffffffffu, runS0, 16);
    runS1 += __shfl_xor_sync(0xffffffffu, runS1, 16);
    runS2 += __shfl_xor_sync(0xffffffffu, runS2, 16);
    runS3 += __shfl_xor_sync(0xffffffffu, runS3, 16);
    runQ0 += __shfl_xor_sync(0xffffffffu, runQ0, 16);
    runQ1 += __shfl_xor_sync(0xffffffffu, runQ1, 16);
    runQ2 += __shfl_xor_sync(0xffffffffu, runQ2, 16);
    runQ3 += __shfl_xor_sync(0xffffffffu, runQ3, 16);

    if (lane == 0) {
        sPart[w][0] = runS0; sPart[w][1] = runS1;
        sPart[w][2] = runS2; sPart[w][3] = runS3;
        sPart[w][4] = runQ0; sPart[w][5] = runQ1;
        sPart[w][6] = runQ2; sPart[w][7] = runQ3;
    }
    __syncthreads();

    if (tid < 8) {
        float t = sPart[0][tid] + sPart[1][tid] + sPart[2][tid] + sPart[3][tid];
        g_part[bid * 8 + tid] = t;
    }
    __threadfence();
    if (tid == 0) sTicket = atomicAdd(&g_cnt, 1u);
    __syncthreads();

    if ((sTicket % GRIDX) == GRIDX - 1) {
        __threadfence();
        float* sRed = reinterpret_cast<float*>(sU);   // 512-float scratch
        {
            int ch = tid & 7, row = tid >> 3;          // 16 rows x 8 channels
            float s = 0.f;
            for (int q = row; q < GRIDX; q += 16) s += __ldcg(&g_part[q*8 + ch]);
            sRed[row*8 + ch] = s;
        }
        __syncthreads();
        if (tid < 8) {
            float tt = 0.f;
            #pragma unroll
            for (int r = 0; r < 16; r++) tt += sRed[r*8 + tid];
            sRed[128 + tid] = tt;
        }
        __syncthreads();
        if (tid < 4) {
            float invB = 1.0f / (float)B;
            float mu  = sRed[128 + tid] * invB;
            float var = sRed[132 + tid] * invB - mu*mu;    // biased var
            float scw = gamma[tid] * rsqrtf(var + 1e-5f);
            g_scale[tid]     = scw;
            g_scale[4 + tid] = beta[tid] - mu * scw;
        }
        __threadfence();
        __syncthreads();
        if (tid == 0) atomicAdd(&g_flag, 1u);   // bump epoch
    }

    // ---- all blocks: wait for epoch bump ----
    if (tid == 0) {
        while (*(volatile unsigned*)&g_flag == epoch) __nanosleep(64);
    }
    __syncthreads();
    __threadfence();

    if (tid < 8) sScale[tid] = *(volatile float*)&g_scale[tid];
    __syncthreads();

    // ---- normalize static sample range for this block ----
    {
        const int p0 = (int)(((long)bid * NPAIRS) / GRIDX);
        const int p1 = (int)(((long)(bid + 1) * NPAIRS) / GRIDX);
        float4 scv = *reinterpret_cast<const float4*>(&sScale[0]);
        float4 shv = *reinterpret_cast<const float4*>(&sScale[4]);
        for (int i = 2*p0 + tid; i < 2*p1; i += 128) {
            float4 r = reinterpret_cast<float4*>(out)[i];
            r.x = r.x*scv.x + shv.x;
            r.y = r.y*scv.y + shv.y;
            r.z = r.z*scv.z + shv.z;
            r.w = r.w*scv.w + shv.w;
            reinterpret_cast<float4*>(out)[i] = r;
        }
    }
}

// ---------------- launch ----------------------------------------------------
extern "C" void kernel_launch(void* const* d_in, const int* in_sizes, int n_in,
                              void* d_out, int out_size)
{
    const float* x     = (const float*)d_in[0];  // [B,1,28,28]
    const float* W     = (const float*)d_in[1];  // [16,4]
    const float* b     = (const float*)d_in[2];  // [4]
    const float* vp    = (const float*)d_in[3];  // [3,4,3]
    const float* gamma = (const float*)d_in[4];  // [4]
    const float* beta  = (const float*)d_in[5];  // [4]
    float* out = (float*)d_out;                  // [B,4]

    int B = in_sizes[0] / 784;                   // 65536

    k_all<<<GRIDX, 128>>>(x, W, b, vp, gamma, beta, out, B);
}